// round 15
// baseline (speedup 1.0000x reference)
#include <cuda_runtime.h>
#include <cuda_fp16.h>

#define NMAX 50000
#define EMAX 800000
#define E2MAX (EMAX + NMAX)
#define HC 160
#define NH 5
#define NC 32
#define WPB 8
#define POSB 14

// ---- scratch (static device globals; zero-initialized at load) ----
__device__ __align__(16) float g_nA[NMAX * 16];     // per node: [as1[5] | x[5] | pad]
__device__ float g_ad1[NMAX * NH];
__device__ __align__(16) __half g_h2h[NMAX * 8];    // h2 (fp16), 16B/node
__device__ float g_ad2[NMAX * NH];
__device__ float g_ce1[NH], g_ce2[NH];
__device__ float g_wasad[5 * 16];
__device__ float g_easum;
__device__ __align__(16) int g_cnt[NMAX];           // starts zero; re-zeroed by k_scan
__device__ int   g_rowptr[NMAX + 1];
__device__ int   g_pos[E2MAX];                      // packed: (d << POSB) | pos
__device__ __align__(8) int2 g_edge[E2MAX];         // {src, ea-bits}

// ---- pre (1 block): easum zero + attention constant tables ----
__global__ void k_pre(const float* __restrict__ We1, const float* __restrict__ ae1,
                      const float* __restrict__ We2, const float* __restrict__ ae2,
                      const float* __restrict__ W1,
                      const float* __restrict__ a_src1, const float* __restrict__ a_dst1) {
    int t = threadIdx.x;
    if (t == 0) g_easum = 0.f;
    if (t < NH) {
        float s = 0.f;
        for (int c = 0; c < NC; c++) s += We1[t * NC + c] * ae1[t * NC + c];
        g_ce1[t] = s;
        g_ce2[t] = We2[t] * ae2[t];
    }
    if (t >= 64 && t < 114) {
        int u = t - 64;
        int f = u / 10, j = u % 10;
        int h = (j < 5) ? j : j - 5;
        const float* a = (j < 5) ? a_src1 : a_dst1;
        float s = 0.f;
        for (int c = 0; c < NC; c++) s += W1[f * HC + h * NC + c] * a[h * NC + c];
        g_wasad[f * 16 + j] = s;
    }
}

// ---- combo: [count in-degree + easum] || [node records: as1/ad1/x] ----
__global__ void k_combo(const int* __restrict__ dst, const float* __restrict__ ea,
                        const float* __restrict__ x,
                        int E, int N, int countBlocks) {
    if ((int)blockIdx.x < countBlocks) {
        int e = blockIdx.x * blockDim.x + threadIdx.x;
        int E2 = E + N;
        float s = 0.f;
        if (e < E2) {
            int d = (e < E) ? __ldg(&dst[e]) : (e - E);
            int pos = atomicAdd(&g_cnt[d], 1);
            g_pos[e] = (d << POSB) | pos;
            if (e < E) s = __ldg(&ea[e]);
        }
        #pragma unroll
        for (int o = 16; o; o >>= 1) s += __shfl_xor_sync(~0u, s, o);
        if ((threadIdx.x & 31) == 0 && s != 0.f) atomicAdd(&g_easum, s);
    } else {
        __shared__ float sw[80];
        if (threadIdx.x < 80) sw[threadIdx.x] = g_wasad[threadIdx.x];
        __syncthreads();
        int n = ((int)blockIdx.x - countBlocks) * blockDim.x + threadIdx.x;
        if (n >= N) return;
        float xf[5];
        #pragma unroll
        for (int f = 0; f < 5; f++) xf[f] = __ldg(&x[n * 5 + f]);
        float as[NH], ad[NH];
        #pragma unroll
        for (int h = 0; h < NH; h++) {
            float a = 0.f, b = 0.f;
            #pragma unroll
            for (int f = 0; f < 5; f++) {
                a = fmaf(xf[f], sw[f * 16 + h], a);
                b = fmaf(xf[f], sw[f * 16 + 5 + h], b);
            }
            as[h] = a; ad[h] = b;
        }
        float4* rowp = (float4*)(g_nA + n * 16);
        float4 r0; r0.x = as[0]; r0.y = as[1]; r0.z = as[2]; r0.w = as[3];
        float4 r1; r1.x = as[4]; r1.y = xf[0]; r1.z = xf[1]; r1.w = xf[2];
        float4 r2; r2.x = xf[3]; r2.y = xf[4]; r2.z = 0.f; r2.w = 0.f;
        rowp[0] = r0; rowp[1] = r1; rowp[2] = r2;
        #pragma unroll
        for (int h = 0; h < NH; h++) g_ad1[n * NH + h] = ad[h];
    }
}

// ---- single-block exclusive scan; also re-zeroes g_cnt for next replay ----
__global__ void k_scan(int N, int E2) {
    __shared__ int wsum[32];
    int t = threadIdx.x;
    int lane = t & 31, w = t >> 5;
    int chunk = ((N + 1023) / 1024 + 3) & ~3;
    int b = t * chunk, e = min(b + chunk, N);
    int s = 0;
    int i = b;
    for (; i + 3 < e; i += 4) {
        int4 v = *(const int4*)(g_cnt + i);
        s += v.x + v.y + v.z + v.w;
    }
    for (; i < e; i++) s += g_cnt[i];
    int inc = s;
    #pragma unroll
    for (int o = 1; o < 32; o <<= 1) {
        int v = __shfl_up_sync(~0u, inc, o);
        if (lane >= o) inc += v;
    }
    if (lane == 31) wsum[w] = inc;
    __syncthreads();
    if (w == 0) {
        int v = wsum[lane];
        int iv = v;
        #pragma unroll
        for (int o = 1; o < 32; o <<= 1) {
            int u = __shfl_up_sync(~0u, iv, o);
            if (lane >= o) iv += u;
        }
        wsum[lane] = iv - v;
    }
    __syncthreads();
    int run = wsum[w] + inc - s;
    for (int j = b; j < e; j++) {
        g_rowptr[j] = run;
        run += g_cnt[j];
        g_cnt[j] = 0;          // ready for next graph replay
    }
    if (t == 0) g_rowptr[N] = E2;
}

// ---- scatter edges into CSR: atomic-free, packed pos ----
__global__ void k_scatter(const int* __restrict__ src,
                          const float* __restrict__ ea, int E, int N, float invE) {
    int e = blockIdx.x * blockDim.x + threadIdx.x;
    int E2 = E + N;
    if (e >= E2) return;
    int pk = g_pos[e];
    int d = pk >> POSB;
    int pos = pk & ((1 << POSB) - 1);
    int s; float av;
    if (e < E) { s = __ldg(&src[e]); av = __ldg(&ea[e]); }
    else       { s = e - E; av = g_easum * invE; }
    int2 rec; rec.x = s; rec.y = __float_as_int(av);
    g_edge[__ldg(&g_rowptr[d]) + pos] = rec;
}

// ---- FUSED1: layer1 softmax+agg (factored S) + relu + layer2 transform ----
__global__ void __launch_bounds__(256, 6)
k_fused1(const float* __restrict__ b1, const float* __restrict__ W1,
         const float* __restrict__ W2,
         const float* __restrict__ as2w, const float* __restrict__ ad2w,
         int N) {
    __shared__ __align__(16) float s_rec[WPB][32][12];
    __shared__ float s_S[WPB][32];
    int warp = (blockIdx.x * blockDim.x + threadIdx.x) >> 5;
    int lane = threadIdx.x & 31;
    int w = (threadIdx.x >> 5);
    if (warp >= N) return;
    int n = warp;
    int row = g_rowptr[n], end = g_rowptr[n + 1];

    float adh[NH], ceh[NH];
    #pragma unroll
    for (int h = 0; h < NH; h++) {
        adh[h] = __ldg(&g_ad1[n * NH + h]);
        ceh[h] = g_ce1[h];
    }

    int myh = (lane < 25) ? (lane / 5) : (lane - 25);
    int myf = (lane < 25) ? (lane % 5) : 5;
    float Sacc = 0.f;

    for (int base = row; base < end; base += 32) {
        int cnt = min(32, end - base);
        if (lane < cnt) {
            int2 r = g_edge[base + lane];
            int sA = r.x;
            float av = __int_as_float(r.y);
            const float4* rowp = (const float4*)(g_nA + sA * 16);
            float4 A = __ldg(rowp);
            float4 B = __ldg(rowp + 1);
            float4 C = __ldg(rowp + 2);
            float asv[NH] = {A.x, A.y, A.z, A.w, B.x};
            float ex[NH];
            #pragma unroll
            for (int h = 0; h < NH; h++) {
                float l = asv[h] + adh[h] + av * ceh[h];
                l = l > 0.f ? l : 0.2f * l;
                ex[h] = __expf(l);
            }
            float4* rec = (float4*)s_rec[w][lane];
            float4 p0; p0.x = ex[0]; p0.y = ex[1]; p0.z = ex[2]; p0.w = ex[3];
            float4 p1; p1.x = ex[4]; p1.y = B.y; p1.z = B.z; p1.w = B.w;
            float4 p2; p2.x = C.x; p2.y = C.y; p2.z = 1.0f; p2.w = 0.f;
            rec[0] = p0; rec[1] = p1; rec[2] = p2;
        }
        __syncwarp();
        if (lane < 30) {
            int j = 0;
            #pragma unroll 2
            for (; j < cnt; j++)
                Sacc = fmaf(s_rec[w][j][myh], s_rec[w][j][5 + myf], Sacc);
        }
        __syncwarp();
    }

    if (lane < 30) s_S[w][lane] = Sacc;
    __syncwarp();

    float dinv[NH];
    #pragma unroll
    for (int h = 0; h < NH; h++) dinv[h] = 1.0f / (s_S[w][25 + h] + 1e-16f);

    float a2h[NH] = {0.f, 0.f, 0.f, 0.f, 0.f};
    #pragma unroll
    for (int i = 0; i < 5; i++) {
        int k = i * NC + lane;
        float msg = 0.f;
        #pragma unroll
        for (int f = 0; f < 5; f++)
            msg = fmaf(s_S[w][i * 5 + f], __ldg(&W1[f * HC + k]), msg);
        float v = msg * dinv[i] + __ldg(&b1[k]);
        v = fmaxf(v, 0.f);
        #pragma unroll
        for (int h = 0; h < NH; h++)
            a2h[h] = fmaf(v, __ldg(&W2[k * NH + h]), a2h[h]);
    }
    #pragma unroll
    for (int h = 0; h < NH; h++)
        #pragma unroll
        for (int o = 16; o; o >>= 1) a2h[h] += __shfl_xor_sync(~0u, a2h[h], o);
    if (lane == 0) {
        __half2 q0 = __floats2half2_rn(a2h[0], a2h[1]);
        __half2 q1 = __floats2half2_rn(a2h[2], a2h[3]);
        __half2 q2 = __floats2half2_rn(a2h[4], 0.f);
        __half2 q3 = __floats2half2_rn(0.f, 0.f);
        int4 pk;
        pk.x = *(int*)&q0; pk.y = *(int*)&q1; pk.z = *(int*)&q2; pk.w = *(int*)&q3;
        *(int4*)(g_h2h + n * 8) = pk;
        #pragma unroll
        for (int h = 0; h < NH; h++)
            g_ad2[n * NH + h] = a2h[h] * __ldg(&ad2w[h]);
    }
}

// ---- FUSED2: layer2 softmax+agg + head-mean + Wlin + sigmoid ----
__global__ void k_fused2(const float* __restrict__ as2w,
                         const float* __restrict__ b2, const float* __restrict__ Wlin,
                         float* __restrict__ out, int N) {
    int warp = (blockIdx.x * blockDim.x + threadIdx.x) >> 5;
    int lane = threadIdx.x & 31;
    if (warp >= N) return;
    int n = warp;
    int row = g_rowptr[n], end = g_rowptr[n + 1];

    float adh[NH], ceh[NH], aw[NH];
    #pragma unroll
    for (int h = 0; h < NH; h++) {
        adh[h] = __ldg(&g_ad2[n * NH + h]);
        ceh[h] = g_ce2[h];
        aw[h]  = __ldg(&as2w[h]);
    }
    float acch[NH] = {0.f, 0.f, 0.f, 0.f, 0.f};
    float denh[NH] = {0.f, 0.f, 0.f, 0.f, 0.f};

    for (int base = row; base < end; base += 32) {
        int e = base + lane;
        if (e < end) {
            int2 r = g_edge[e];
            int s = r.x;
            float av = __int_as_float(r.y);
            int4 vp = __ldg((const int4*)(g_h2h + s * 8));
            float2 f01 = __half22float2(*(__half2*)&vp.x);
            float2 f23 = __half22float2(*(__half2*)&vp.y);
            float2 f45 = __half22float2(*(__half2*)&vp.z);
            float h2v[NH] = {f01.x, f01.y, f23.x, f23.y, f45.x};
            #pragma unroll
            for (int h = 0; h < NH; h++) {
                float l = fmaf(h2v[h], aw[h], adh[h] + av * ceh[h]);
                l = l > 0.f ? l : 0.2f * l;
                float ex = __expf(l);
                denh[h] += ex;
                acch[h] = fmaf(ex, h2v[h], acch[h]);
            }
        }
    }
    #pragma unroll
    for (int h = 0; h < NH; h++)
        #pragma unroll
        for (int o = 16; o; o >>= 1) {
            acch[h] += __shfl_xor_sync(~0u, acch[h], o);
            denh[h] += __shfl_xor_sync(~0u, denh[h], o);
        }
    if (lane == 0) {
        float ssum = 0.f;
        #pragma unroll
        for (int h = 0; h < NH; h++) ssum += acch[h] / (denh[h] + 1e-16f);
        float y = (ssum * (1.0f / NH) + __ldg(&b2[0])) * __ldg(&Wlin[0]);
        out[n] = 1.0f / (1.0f + expf(-y));
    }
}

extern "C" void kernel_launch(void* const* d_in, const int* in_sizes, int n_in,
                              void* d_out, int out_size) {
    const float* x      = (const float*)d_in[0];
    const float* ea     = (const float*)d_in[1];
    const int*   src    = (const int*)d_in[2];
    const int*   dst    = (const int*)d_in[3];
    const float* W1     = (const float*)d_in[4];
    const float* a_src1 = (const float*)d_in[5];
    const float* a_dst1 = (const float*)d_in[6];
    const float* We1    = (const float*)d_in[7];
    const float* ae1    = (const float*)d_in[8];
    const float* b1     = (const float*)d_in[9];
    const float* W2     = (const float*)d_in[10];
    const float* a_src2 = (const float*)d_in[11];
    const float* a_dst2 = (const float*)d_in[12];
    const float* We2    = (const float*)d_in[13];
    const float* ae2    = (const float*)d_in[14];
    const float* b2     = (const float*)d_in[15];
    const float* Wlin   = (const float*)d_in[16];

    int N  = in_sizes[0] / 5;
    int E  = in_sizes[2];
    int E2 = E + N;
    float invE = 1.0f / (float)E;

    int countBlocks = (E2 + 255) / 256;
    int nodeBlocks  = (N + 255) / 256;
    k_pre<<<1, 128>>>(We1, ae1, We2, ae2, W1, a_src1, a_dst1);
    k_combo<<<countBlocks + nodeBlocks, 256>>>(dst, ea, x, E, N, countBlocks);
    k_scan<<<1, 1024>>>(N, E2);
    k_scatter<<<(E2 + 255) / 256, 256>>>(src, ea, E, N, invE);
    k_fused1<<<(N * 32 + 255) / 256, 256>>>(b1, W1, W2, a_src2, a_dst2, N);
    k_fused2<<<(N * 32 + 255) / 256, 256>>>(a_src2, b2, Wlin, (float*)d_out, N);
}

// round 16
// speedup vs baseline: 1.2112x; 1.2112x over previous
#include <cuda_runtime.h>
#include <cuda_fp16.h>

#define NMAX 50000
#define EMAX 800000
#define E2MAX (EMAX + NMAX)
#define HC 160
#define NH 5
#define NC 32
#define WPB 8
#define POSB 14

// ---- scratch (static device globals) ----
__device__ __align__(16) float g_nA[NMAX * 16];     // per node: [as1[5] | x[5] | pad] (64B row)
__device__ float g_ad1[NMAX * NH];
__device__ __align__(16) __half g_h2h[NMAX * 8];    // h2 (fp16), 16B/node
__device__ float g_ad2[NMAX * NH];
__device__ float g_ce1[NH], g_ce2[NH];
__device__ float g_wasad[5 * 16];
__device__ float g_easum;
__device__ __align__(16) int g_cnt[NMAX];
__device__ int   g_rowptr[NMAX + 1];
__device__ int   g_pos[E2MAX];                      // packed: (d << POSB) | pos
__device__ __align__(8) int2 g_edge[E2MAX];         // {src, ea-bits}

// ---- pre: zero counters + attention constant tables ----
__global__ void k_pre(const float* __restrict__ We1, const float* __restrict__ ae1,
                      const float* __restrict__ We2, const float* __restrict__ ae2,
                      const float* __restrict__ W1,
                      const float* __restrict__ a_src1, const float* __restrict__ a_dst1,
                      int N) {
    int i = blockIdx.x * blockDim.x + threadIdx.x;
    if (i < N) g_cnt[i] = 0;
    if (blockIdx.x == 0) {
        int t = threadIdx.x;
        if (t == 0) g_easum = 0.f;
        if (t < NH) {
            float s = 0.f;
            for (int c = 0; c < NC; c++) s += We1[t * NC + c] * ae1[t * NC + c];
            g_ce1[t] = s;
            g_ce2[t] = We2[t] * ae2[t];
        }
        if (t >= 64 && t < 114) {
            int u = t - 64;
            int f = u / 10, j = u % 10;
            int h = (j < 5) ? j : j - 5;
            const float* a = (j < 5) ? a_src1 : a_dst1;
            float s = 0.f;
            for (int c = 0; c < NC; c++) s += W1[f * HC + h * NC + c] * a[h * NC + c];
            g_wasad[f * 16 + j] = s;
        }
    }
}

// ---- combo: [count in-degree + easum] || [node records: as1/ad1/x] ----
__global__ void k_combo(const int* __restrict__ dst, const float* __restrict__ ea,
                        const float* __restrict__ x,
                        int E, int N, int countBlocks) {
    if ((int)blockIdx.x < countBlocks) {
        int e = blockIdx.x * blockDim.x + threadIdx.x;
        int E2 = E + N;
        float s = 0.f;
        if (e < E2) {
            int d = (e < E) ? __ldg(&dst[e]) : (e - E);
            int pos = atomicAdd(&g_cnt[d], 1);
            g_pos[e] = (d << POSB) | pos;
            if (e < E) s = __ldg(&ea[e]);
        }
        #pragma unroll
        for (int o = 16; o; o >>= 1) s += __shfl_xor_sync(~0u, s, o);
        if ((threadIdx.x & 31) == 0 && s != 0.f) atomicAdd(&g_easum, s);
    } else {
        __shared__ float sw[80];
        if (threadIdx.x < 80) sw[threadIdx.x] = g_wasad[threadIdx.x];
        __syncthreads();
        int n = ((int)blockIdx.x - countBlocks) * blockDim.x + threadIdx.x;
        if (n >= N) return;
        float xf[5];
        #pragma unroll
        for (int f = 0; f < 5; f++) xf[f] = __ldg(&x[n * 5 + f]);
        float as[NH], ad[NH];
        #pragma unroll
        for (int h = 0; h < NH; h++) {
            float a = 0.f, b = 0.f;
            #pragma unroll
            for (int f = 0; f < 5; f++) {
                a = fmaf(xf[f], sw[f * 16 + h], a);
                b = fmaf(xf[f], sw[f * 16 + 5 + h], b);
            }
            as[h] = a; ad[h] = b;
        }
        float4* rowp = (float4*)(g_nA + n * 16);
        float4 r0; r0.x = as[0]; r0.y = as[1]; r0.z = as[2]; r0.w = as[3];
        float4 r1; r1.x = as[4]; r1.y = xf[0]; r1.z = xf[1]; r1.w = xf[2];
        float4 r2; r2.x = xf[3]; r2.y = xf[4]; r2.z = 0.f; r2.w = 0.f;
        rowp[0] = r0; rowp[1] = r1; rowp[2] = r2;
        #pragma unroll
        for (int h = 0; h < NH; h++) g_ad1[n * NH + h] = ad[h];
    }
}

// ---- single-block exclusive scan (int4-vectorized partial sums) ----
__global__ void k_scan(int N, int E2) {
    __shared__ int wsum[32];
    int t = threadIdx.x;
    int lane = t & 31, w = t >> 5;
    int chunk = ((N + 1023) / 1024 + 3) & ~3;
    int b = t * chunk, e = min(b + chunk, N);
    int s = 0;
    int i = b;
    for (; i + 3 < e; i += 4) {
        int4 v = *(const int4*)(g_cnt + i);
        s += v.x + v.y + v.z + v.w;
    }
    for (; i < e; i++) s += g_cnt[i];
    int inc = s;
    #pragma unroll
    for (int o = 1; o < 32; o <<= 1) {
        int v = __shfl_up_sync(~0u, inc, o);
        if (lane >= o) inc += v;
    }
    if (lane == 31) wsum[w] = inc;
    __syncthreads();
    if (w == 0) {
        int v = wsum[lane];
        int iv = v;
        #pragma unroll
        for (int o = 1; o < 32; o <<= 1) {
            int u = __shfl_up_sync(~0u, iv, o);
            if (lane >= o) iv += u;
        }
        wsum[lane] = iv - v;
    }
    __syncthreads();
    int run = wsum[w] + inc - s;
    for (int j = b; j < e; j++) {
        g_rowptr[j] = run;
        run += g_cnt[j];
    }
    if (t == 0) g_rowptr[N] = E2;
}

// ---- scatter edges into CSR: atomic-free, packed pos ----
__global__ void k_scatter(const int* __restrict__ src,
                          const float* __restrict__ ea, int E, int N, float invE) {
    int e = blockIdx.x * blockDim.x + threadIdx.x;
    int E2 = E + N;
    if (e >= E2) return;
    int pk = g_pos[e];
    int d = pk >> POSB;
    int pos = pk & ((1 << POSB) - 1);
    int s; float av;
    if (e < E) { s = __ldg(&src[e]); av = __ldg(&ea[e]); }
    else       { s = e - E; av = g_easum * invE; }
    int2 rec; rec.x = s; rec.y = __float_as_int(av);
    g_edge[__ldg(&g_rowptr[d]) + pos] = rec;
}

// ---- FUSED1: layer1 softmax+agg (factored via S = sum ex*x) + relu + layer2 ----
__global__ void __launch_bounds__(256, 6)
k_fused1(const float* __restrict__ b1, const float* __restrict__ W1,
         const float* __restrict__ W2,
         const float* __restrict__ as2w, const float* __restrict__ ad2w,
         int N) {
    __shared__ __align__(16) float s_rec[WPB][32][12];
    __shared__ float s_S[WPB][32];
    int warp = (blockIdx.x * blockDim.x + threadIdx.x) >> 5;
    int lane = threadIdx.x & 31;
    int w = (threadIdx.x >> 5);
    if (warp >= N) return;
    int n = warp;
    int row = g_rowptr[n], end = g_rowptr[n + 1];

    float adh[NH], ceh[NH];
    #pragma unroll
    for (int h = 0; h < NH; h++) {
        adh[h] = __ldg(&g_ad1[n * NH + h]);
        ceh[h] = g_ce1[h];
    }

    int myh = (lane < 25) ? (lane / 5) : (lane - 25);
    int myf = (lane < 25) ? (lane % 5) : 5;
    float Sacc = 0.f;

    for (int base = row; base < end; base += 32) {
        int cnt = min(32, end - base);
        if (lane < cnt) {
            int2 r = g_edge[base + lane];
            int sA = r.x;
            float av = __int_as_float(r.y);
            const float4* rowp = (const float4*)(g_nA + sA * 16);
            float4 A = __ldg(rowp);
            float4 B = __ldg(rowp + 1);
            float4 C = __ldg(rowp + 2);
            float asv[NH] = {A.x, A.y, A.z, A.w, B.x};
            float ex[NH];
            #pragma unroll
            for (int h = 0; h < NH; h++) {
                float l = asv[h] + adh[h] + av * ceh[h];
                l = l > 0.f ? l : 0.2f * l;
                ex[h] = __expf(l);
            }
            float4* rec = (float4*)s_rec[w][lane];
            float4 p0; p0.x = ex[0]; p0.y = ex[1]; p0.z = ex[2]; p0.w = ex[3];
            float4 p1; p1.x = ex[4]; p1.y = B.y; p1.z = B.z; p1.w = B.w;
            float4 p2; p2.x = C.x; p2.y = C.y; p2.z = 1.0f; p2.w = 0.f;
            rec[0] = p0; rec[1] = p1; rec[2] = p2;
        }
        __syncwarp();
        if (lane < 30) {
            int j = 0;
            #pragma unroll 2
            for (; j < cnt; j++)
                Sacc = fmaf(s_rec[w][j][myh], s_rec[w][j][5 + myf], Sacc);
        }
        __syncwarp();
    }

    if (lane < 30) s_S[w][lane] = Sacc;
    __syncwarp();

    float dinv[NH];
    #pragma unroll
    for (int h = 0; h < NH; h++) dinv[h] = 1.0f / (s_S[w][25 + h] + 1e-16f);

    float a2h[NH] = {0.f, 0.f, 0.f, 0.f, 0.f};
    #pragma unroll
    for (int i = 0; i < 5; i++) {
        int k = i * NC + lane;
        float msg = 0.f;
        #pragma unroll
        for (int f = 0; f < 5; f++)
            msg = fmaf(s_S[w][i * 5 + f], __ldg(&W1[f * HC + k]), msg);
        float v = msg * dinv[i] + __ldg(&b1[k]);
        v = fmaxf(v, 0.f);
        #pragma unroll
        for (int h = 0; h < NH; h++)
            a2h[h] = fmaf(v, __ldg(&W2[k * NH + h]), a2h[h]);
    }
    #pragma unroll
    for (int h = 0; h < NH; h++)
        #pragma unroll
        for (int o = 16; o; o >>= 1) a2h[h] += __shfl_xor_sync(~0u, a2h[h], o);
    if (lane == 0) {
        __half2 q0 = __floats2half2_rn(a2h[0], a2h[1]);
        __half2 q1 = __floats2half2_rn(a2h[2], a2h[3]);
        __half2 q2 = __floats2half2_rn(a2h[4], 0.f);
        __half2 q3 = __floats2half2_rn(0.f, 0.f);
        int4 pk;
        pk.x = *(int*)&q0; pk.y = *(int*)&q1; pk.z = *(int*)&q2; pk.w = *(int*)&q3;
        *(int4*)(g_h2h + n * 8) = pk;
        #pragma unroll
        for (int h = 0; h < NH; h++)
            g_ad2[n * NH + h] = a2h[h] * __ldg(&ad2w[h]);
    }
}

// ---- FUSED2: layer2 softmax+agg + head-mean + Wlin + sigmoid ----
__global__ void k_fused2(const float* __restrict__ as2w,
                         const float* __restrict__ b2, const float* __restrict__ Wlin,
                         float* __restrict__ out, int N) {
    int warp = (blockIdx.x * blockDim.x + threadIdx.x) >> 5;
    int lane = threadIdx.x & 31;
    if (warp >= N) return;
    int n = warp;
    int row = g_rowptr[n], end = g_rowptr[n + 1];

    float adh[NH], ceh[NH], aw[NH];
    #pragma unroll
    for (int h = 0; h < NH; h++) {
        adh[h] = __ldg(&g_ad2[n * NH + h]);
        ceh[h] = g_ce2[h];
        aw[h]  = __ldg(&as2w[h]);
    }
    float acch[NH] = {0.f, 0.f, 0.f, 0.f, 0.f};
    float denh[NH] = {0.f, 0.f, 0.f, 0.f, 0.f};

    for (int base = row; base < end; base += 32) {
        int e = base + lane;
        if (e < end) {
            int2 r = g_edge[e];
            int s = r.x;
            float av = __int_as_float(r.y);
            int4 vp = __ldg((const int4*)(g_h2h + s * 8));
            float2 f01 = __half22float2(*(__half2*)&vp.x);
            float2 f23 = __half22float2(*(__half2*)&vp.y);
            float2 f45 = __half22float2(*(__half2*)&vp.z);
            float h2v[NH] = {f01.x, f01.y, f23.x, f23.y, f45.x};
            #pragma unroll
            for (int h = 0; h < NH; h++) {
                float l = fmaf(h2v[h], aw[h], adh[h] + av * ceh[h]);
                l = l > 0.f ? l : 0.2f * l;
                float ex = __expf(l);
                denh[h] += ex;
                acch[h] = fmaf(ex, h2v[h], acch[h]);
            }
        }
    }
    #pragma unroll
    for (int h = 0; h < NH; h++)
        #pragma unroll
        for (int o = 16; o; o >>= 1) {
            acch[h] += __shfl_xor_sync(~0u, acch[h], o);
            denh[h] += __shfl_xor_sync(~0u, denh[h], o);
        }
    if (lane == 0) {
        float ssum = 0.f;
        #pragma unroll
        for (int h = 0; h < NH; h++) ssum += acch[h] / (denh[h] + 1e-16f);
        float y = (ssum * (1.0f / NH) + __ldg(&b2[0])) * __ldg(&Wlin[0]);
        out[n] = 1.0f / (1.0f + expf(-y));
    }
}

extern "C" void kernel_launch(void* const* d_in, const int* in_sizes, int n_in,
                              void* d_out, int out_size) {
    const float* x      = (const float*)d_in[0];
    const float* ea     = (const float*)d_in[1];
    const int*   src    = (const int*)d_in[2];
    const int*   dst    = (const int*)d_in[3];
    const float* W1     = (const float*)d_in[4];
    const float* a_src1 = (const float*)d_in[5];
    const float* a_dst1 = (const float*)d_in[6];
    const float* We1    = (const float*)d_in[7];
    const float* ae1    = (const float*)d_in[8];
    const float* b1     = (const float*)d_in[9];
    const float* W2     = (const float*)d_in[10];
    const float* a_src2 = (const float*)d_in[11];
    const float* a_dst2 = (const float*)d_in[12];
    const float* We2    = (const float*)d_in[13];
    const float* ae2    = (const float*)d_in[14];
    const float* b2     = (const float*)d_in[15];
    const float* Wlin   = (const float*)d_in[16];

    int N  = in_sizes[0] / 5;
    int E  = in_sizes[2];
    int E2 = E + N;
    float invE = 1.0f / (float)E;

    int countBlocks = (E2 + 255) / 256;
    int nodeBlocks  = (N + 255) / 256;
    k_pre<<<(N + 255) / 256, 256>>>(We1, ae1, We2, ae2, W1, a_src1, a_dst1, N);
    k_combo<<<countBlocks + nodeBlocks, 256>>>(dst, ea, x, E, N, countBlocks);
    k_scan<<<1, 1024>>>(N, E2);
    k_scatter<<<(E2 + 255) / 256, 256>>>(src, ea, E, N, invE);
    k_fused1<<<(N * 32 + 255) / 256, 256>>>(b1, W1, W2, a_src2, a_dst2, N);
    k_fused2<<<(N * 32 + 255) / 256, 256>>>(a_src2, b2, Wlin, (float*)d_out, N);
}

// round 17
// speedup vs baseline: 1.9762x; 1.6316x over previous
#include <cuda_runtime.h>
#include <cuda_fp16.h>

#define NMAX 50000
#define EMAX 800000
#define HC 160
#define NH 5
#define NC 32
#define WPB 8

// ---- scratch (static device globals; zero-initialized at load) ----
__device__ __align__(16) float g_nA[NMAX * 16];   // [as1[5] | x[5] | ad1[5] | pad]
__device__ __align__(16) float g_S1[NMAX * 32];   // layer1 atomic accum (zero; re-zeroed by fin1)
__device__ __align__(16) __half g_h2h[NMAX * 8];  // h2 fp16, 16B/node
__device__ __align__(16) float g_ad2[NMAX * 8];   // ad2 padded to 8 floats
__device__ __align__(16) float g_D2[NMAX * 12];   // layer2 atomic accum (zero; re-zeroed by fin2)
__device__ float g_ce1[NH], g_ce2[NH];
__device__ float g_wasad[5 * 16];
__device__ float g_easum;

__device__ __forceinline__ float lrelu(float l) { return l > 0.f ? l : 0.2f * l; }

#define RED4(ptr, a, b, c, d) \
    asm volatile("red.global.add.v4.f32 [%0], {%1,%2,%3,%4};" \
                 :: "l"(ptr), "f"(a), "f"(b), "f"(c), "f"(d) : "memory")

// ---- pre (1 block): easum=0 + constant tables ----
__global__ void k_pre(const float* __restrict__ We1, const float* __restrict__ ae1,
                      const float* __restrict__ We2, const float* __restrict__ ae2,
                      const float* __restrict__ W1,
                      const float* __restrict__ a_src1, const float* __restrict__ a_dst1) {
    int t = threadIdx.x;
    if (t == 0) g_easum = 0.f;
    if (t < NH) {
        float s = 0.f;
        for (int c = 0; c < NC; c++) s += We1[t * NC + c] * ae1[t * NC + c];
        g_ce1[t] = s;
        g_ce2[t] = We2[t] * ae2[t];
    }
    if (t >= 64 && t < 114) {
        int u = t - 64;
        int f = u / 10, j = u % 10;
        int h = (j < 5) ? j : j - 5;
        const float* a = (j < 5) ? a_src1 : a_dst1;
        float s = 0.f;
        for (int c = 0; c < NC; c++) s += W1[f * HC + h * NC + c] * a[h * NC + c];
        g_wasad[f * 16 + j] = s;
    }
}

// ---- main1: [easum reduction] || [node records as1/x/ad1] ----
__global__ void k_main1(const float* __restrict__ ea, const float* __restrict__ x,
                        int E, int N, int eaBlocks) {
    if ((int)blockIdx.x < eaBlocks) {
        __shared__ float ws[8];
        float s = 0.f;
        int stride = eaBlocks * blockDim.x;
        for (int i = blockIdx.x * blockDim.x + threadIdx.x; i < E; i += stride)
            s += __ldg(&ea[i]);
        #pragma unroll
        for (int o = 16; o; o >>= 1) s += __shfl_xor_sync(~0u, s, o);
        int w = threadIdx.x >> 5;
        if ((threadIdx.x & 31) == 0) ws[w] = s;
        __syncthreads();
        if (threadIdx.x == 0) {
            float t = 0.f;
            #pragma unroll
            for (int i = 0; i < 8; i++) t += ws[i];
            atomicAdd(&g_easum, t);
        }
    } else {
        __shared__ float sw[80];
        if (threadIdx.x < 80) sw[threadIdx.x] = g_wasad[threadIdx.x];
        __syncthreads();
        int n = ((int)blockIdx.x - eaBlocks) * blockDim.x + threadIdx.x;
        if (n >= N) return;
        float xf[5];
        #pragma unroll
        for (int f = 0; f < 5; f++) xf[f] = __ldg(&x[n * 5 + f]);
        float as[NH], ad[NH];
        #pragma unroll
        for (int h = 0; h < NH; h++) {
            float a = 0.f, b = 0.f;
            #pragma unroll
            for (int f = 0; f < 5; f++) {
                a = fmaf(xf[f], sw[f * 16 + h], a);
                b = fmaf(xf[f], sw[f * 16 + 5 + h], b);
            }
            as[h] = a; ad[h] = b;
        }
        float4* rowp = (float4*)(g_nA + n * 16);
        float4 r0; r0.x = as[0]; r0.y = as[1]; r0.z = as[2]; r0.w = as[3];
        float4 r1; r1.x = as[4]; r1.y = xf[0]; r1.z = xf[1]; r1.w = xf[2];
        float4 r2; r2.x = xf[3]; r2.y = xf[4]; r2.z = ad[0]; r2.w = ad[1];
        float4 r3; r3.x = ad[2]; r3.y = ad[3]; r3.z = ad[4]; r3.w = 0.f;
        rowp[0] = r0; rowp[1] = r1; rowp[2] = r2; rowp[3] = r3;
    }
}

// ---- edge1: E-parallel logits + 8x red.v4 into S1[dst] ----
__global__ void k_edge1(const int* __restrict__ src, const int* __restrict__ dst,
                        const float* __restrict__ ea, int E) {
    int e = blockIdx.x * blockDim.x + threadIdx.x;
    if (e >= E) return;
    int s = __ldg(&src[e]);
    int d = __ldg(&dst[e]);
    float av = __ldg(&ea[e]);
    const float4* sr = (const float4*)(g_nA + s * 16);
    float4 A = __ldg(sr), B = __ldg(sr + 1), C = __ldg(sr + 2);
    const float4* dr = (const float4*)(g_nA + d * 16);
    float4 Dq = __ldg(dr + 2), Eq = __ldg(dr + 3);
    float as[NH] = {A.x, A.y, A.z, A.w, B.x};
    float xv[NH] = {B.y, B.z, B.w, C.x, C.y};
    float ad[NH] = {Dq.z, Dq.w, Eq.x, Eq.y, Eq.z};
    float ex[NH];
    #pragma unroll
    for (int h = 0; h < NH; h++)
        ex[h] = __expf(lrelu(as[h] + ad[h] + av * g_ce1[h]));
    float* bp = g_S1 + d * 32;
    // layout: idx h*5+f = ex_h*x_f ; idx 25+h = ex_h ; 30,31 = 0
    RED4(bp + 0,  ex[0]*xv[0], ex[0]*xv[1], ex[0]*xv[2], ex[0]*xv[3]);
    RED4(bp + 4,  ex[0]*xv[4], ex[1]*xv[0], ex[1]*xv[1], ex[1]*xv[2]);
    RED4(bp + 8,  ex[1]*xv[3], ex[1]*xv[4], ex[2]*xv[0], ex[2]*xv[1]);
    RED4(bp + 12, ex[2]*xv[2], ex[2]*xv[3], ex[2]*xv[4], ex[3]*xv[0]);
    RED4(bp + 16, ex[3]*xv[1], ex[3]*xv[2], ex[3]*xv[3], ex[3]*xv[4]);
    RED4(bp + 20, ex[4]*xv[0], ex[4]*xv[1], ex[4]*xv[2], ex[4]*xv[3]);
    RED4(bp + 24, ex[4]*xv[4], ex[0],       ex[1],       ex[2]);
    RED4(bp + 28, ex[3],       ex[4],       0.f,         0.f);
}

// ---- fin1: warp per node. self-loop + S merge + epilogue -> h2h, ad2. ----
__global__ void __launch_bounds__(256, 6)
k_fin1(const float* __restrict__ b1, const float* __restrict__ W1,
       const float* __restrict__ W2,
       const float* __restrict__ as2w, const float* __restrict__ ad2w,
       float invE, int N) {
    __shared__ float s_S[WPB][32];
    int warp = (blockIdx.x * blockDim.x + threadIdx.x) >> 5;
    int lane = threadIdx.x & 31;
    int w = threadIdx.x >> 5;
    if (warp >= N) return;
    int n = warp;
    float eam = g_easum * invE;

    float Sg = g_S1[n * 32 + lane];
    // self-loop exp (lanes 0-4 compute, then broadcast)
    float exs = 0.f;
    if (lane < NH) {
        float asn = g_nA[n * 16 + lane];
        float adn = g_nA[n * 16 + 10 + lane];
        exs = __expf(lrelu(asn + adn + eam * g_ce1[lane]));
    }
    int myh = (lane < 25) ? (lane / 5) : (lane - 25);
    int myf = (lane < 25) ? (lane % 5) : 5;
    float exsh = __shfl_sync(~0u, exs, myh < 5 ? myh : 0);
    float xf = (myf < 5) ? g_nA[n * 16 + 5 + myf] : 1.0f;
    s_S[w][lane] = (lane < 30) ? (Sg + exsh * xf) : 0.f;
    g_S1[n * 32 + lane] = 0.f;   // re-zero for next replay
    __syncwarp();

    float dinv[NH];
    #pragma unroll
    for (int h = 0; h < NH; h++) dinv[h] = 1.0f / (s_S[w][25 + h] + 1e-16f);

    float a2h[NH] = {0.f, 0.f, 0.f, 0.f, 0.f};
    #pragma unroll
    for (int i = 0; i < 5; i++) {
        int k = i * NC + lane;
        float msg = 0.f;
        #pragma unroll
        for (int f = 0; f < 5; f++)
            msg = fmaf(s_S[w][i * 5 + f], __ldg(&W1[f * HC + k]), msg);
        float v = msg * dinv[i] + __ldg(&b1[k]);
        v = fmaxf(v, 0.f);
        #pragma unroll
        for (int h = 0; h < NH; h++)
            a2h[h] = fmaf(v, __ldg(&W2[k * NH + h]), a2h[h]);
    }
    #pragma unroll
    for (int h = 0; h < NH; h++)
        #pragma unroll
        for (int o = 16; o; o >>= 1) a2h[h] += __shfl_xor_sync(~0u, a2h[h], o);
    if (lane == 0) {
        __half2 q0 = __floats2half2_rn(a2h[0], a2h[1]);
        __half2 q1 = __floats2half2_rn(a2h[2], a2h[3]);
        __half2 q2 = __floats2half2_rn(a2h[4], 0.f);
        __half2 q3 = __floats2half2_rn(0.f, 0.f);
        int4 pk;
        pk.x = *(int*)&q0; pk.y = *(int*)&q1; pk.z = *(int*)&q2; pk.w = *(int*)&q3;
        *(int4*)(g_h2h + n * 8) = pk;
        float4 a0; a0.x = a2h[0] * __ldg(&ad2w[0]);
        a0.y = a2h[1] * __ldg(&ad2w[1]);
        a0.z = a2h[2] * __ldg(&ad2w[2]);
        a0.w = a2h[3] * __ldg(&ad2w[3]);
        float4 a1; a1.x = a2h[4] * __ldg(&ad2w[4]); a1.y = 0.f; a1.z = 0.f; a1.w = 0.f;
        float4* ap = (float4*)(g_ad2 + n * 8);
        ap[0] = a0; ap[1] = a1;
    }
}

// ---- edge2: E-parallel layer2 logits + 3x red.v4 into D2[dst] ----
__global__ void k_edge2(const int* __restrict__ src, const int* __restrict__ dst,
                        const float* __restrict__ ea, const float* __restrict__ as2w,
                        int E) {
    int e = blockIdx.x * blockDim.x + threadIdx.x;
    if (e >= E) return;
    int s = __ldg(&src[e]);
    int d = __ldg(&dst[e]);
    float av = __ldg(&ea[e]);
    int4 vp = __ldg((const int4*)(g_h2h + s * 8));
    float2 f01 = __half22float2(*(__half2*)&vp.x);
    float2 f23 = __half22float2(*(__half2*)&vp.y);
    float2 f45 = __half22float2(*(__half2*)&vp.z);
    float h2v[NH] = {f01.x, f01.y, f23.x, f23.y, f45.x};
    const float4* ar = (const float4*)(g_ad2 + d * 8);
    float4 a0 = __ldg(ar), a1 = __ldg(ar + 1);
    float ad[NH] = {a0.x, a0.y, a0.z, a0.w, a1.x};
    float ex[NH];
    #pragma unroll
    for (int h = 0; h < NH; h++)
        ex[h] = __expf(lrelu(fmaf(h2v[h], __ldg(&as2w[h]), ad[h] + av * g_ce2[h])));
    float* bp = g_D2 + d * 12;
    // layout: 0-4 num (ex*h2), 5-9 den (ex), 10-11 pad
    RED4(bp + 0, ex[0]*h2v[0], ex[1]*h2v[1], ex[2]*h2v[2], ex[3]*h2v[3]);
    RED4(bp + 4, ex[4]*h2v[4], ex[0],        ex[1],        ex[2]);
    RED4(bp + 8, ex[3],        ex[4],        0.f,          0.f);
}

// ---- fin2: thread per node. self-loop + mean + Wlin + sigmoid ----
__global__ void k_fin2(const float* __restrict__ as2w,
                       const float* __restrict__ b2, const float* __restrict__ Wlin,
                       float invE, float* __restrict__ out, int N) {
    int n = blockIdx.x * blockDim.x + threadIdx.x;
    if (n >= N) return;
    float eam = g_easum * invE;
    float4* dp = (float4*)(g_D2 + n * 12);
    float4 D0 = dp[0], D1 = dp[1], D2q = dp[2];
    float num[NH] = {D0.x, D0.y, D0.z, D0.w, D1.x};
    float den[NH] = {D1.y, D1.z, D1.w, D2q.x, D2q.y};
    int4 vp = __ldg((const int4*)(g_h2h + n * 8));
    float2 f01 = __half22float2(*(__half2*)&vp.x);
    float2 f23 = __half22float2(*(__half2*)&vp.y);
    float2 f45 = __half22float2(*(__half2*)&vp.z);
    float h2v[NH] = {f01.x, f01.y, f23.x, f23.y, f45.x};
    const float4* ar = (const float4*)(g_ad2 + n * 8);
    float4 a0 = __ldg(ar), a1 = __ldg(ar + 1);
    float ad[NH] = {a0.x, a0.y, a0.z, a0.w, a1.x};
    float ssum = 0.f;
    #pragma unroll
    for (int h = 0; h < NH; h++) {
        float ex = __expf(lrelu(fmaf(h2v[h], __ldg(&as2w[h]), ad[h] + eam * g_ce2[h])));
        num[h] += ex * h2v[h];
        den[h] += ex;
        ssum += num[h] / (den[h] + 1e-16f);
    }
    float y = (ssum * (1.0f / NH) + __ldg(&b2[0])) * __ldg(&Wlin[0]);
    out[n] = 1.0f / (1.0f + expf(-y));
    float4 z; z.x = 0.f; z.y = 0.f; z.z = 0.f; z.w = 0.f;
    dp[0] = z; dp[1] = z; dp[2] = z;   // re-zero for next replay
}

extern "C" void kernel_launch(void* const* d_in, const int* in_sizes, int n_in,
                              void* d_out, int out_size) {
    const float* x      = (const float*)d_in[0];
    const float* ea     = (const float*)d_in[1];
    const int*   src    = (const int*)d_in[2];
    const int*   dst    = (const int*)d_in[3];
    const float* W1     = (const float*)d_in[4];
    const float* a_src1 = (const float*)d_in[5];
    const float* a_dst1 = (const float*)d_in[6];
    const float* We1    = (const float*)d_in[7];
    const float* ae1    = (const float*)d_in[8];
    const float* b1     = (const float*)d_in[9];
    const float* W2     = (const float*)d_in[10];
    const float* a_src2 = (const float*)d_in[11];
    const float* a_dst2 = (const float*)d_in[12];
    const float* We2    = (const float*)d_in[13];
    const float* ae2    = (const float*)d_in[14];
    const float* b2     = (const float*)d_in[15];
    const float* Wlin   = (const float*)d_in[16];

    int N  = in_sizes[0] / 5;
    int E  = in_sizes[2];
    float invE = 1.0f / (float)E;

    int eaBlocks   = (E / (256 * 8) + 1);
    int nodeBlocks = (N + 255) / 256;
    k_pre<<<1, 128>>>(We1, ae1, We2, ae2, W1, a_src1, a_dst1);
    k_main1<<<eaBlocks + nodeBlocks, 256>>>(ea, x, E, N, eaBlocks);
    k_edge1<<<(E + 255) / 256, 256>>>(src, dst, ea, E);
    k_fin1<<<(N * 32 + 255) / 256, 256>>>(b1, W1, W2, a_src2, a_dst2, invE, N);
    k_edge2<<<(E + 255) / 256, 256>>>(src, dst, ea, a_src2, E);
    k_fin2<<<(N + 255) / 256, 256>>>(a_src2, b2, Wlin, invE, (float*)d_out, N);
}